// round 16
// baseline (speedup 1.0000x reference)
#include <cuda_runtime.h>
#include <cuda_bf16.h>

#define NV 8192
#define EPSV 1e-5f
#define SPAN 256            /* fixed bin range: deg in [0,255] */
#define SH 8                /* table row stride = 256 */
#define ECAP (1 << 22)
#define TPB 256
#define NPAIRS (NV / 2)
#define TFILL 64            /* table-fill blocks appended to k_main */
#define NPART 256           /* base-term partition blocks */
#define PSIZE 32            /* NV / NPART */
#define NTRI (PSIZE * (PSIZE + 1) / 2)
#define EBLK 448
#define GRID_BE (NPART + EBLK)
#define NQ (NV / 4)         /* float4s per row = 2048 */

// ---------- device state (static zero-init; reset by k_baseedge finalizer) --
__device__ int      g_deg[NV];
__device__ unsigned g_edges[ECAP];
__device__ int      g_ecount;
__device__ int      g_done;
__device__ double   g_part[GRID_BE];
__device__ float    g_Tbase[SPAN * SPAN];   // log(1-p+eps),  [bj<<8 | bi]
__device__ float    g_Tdiff[SPAN * SPAN];   // log(p+eps)-log(1-p+eps)

// nonzero mask of a 0/1-valued float4 via exact FFMA chain + F2I
__device__ __forceinline__ unsigned nzmask4(float4 v) {
    float m = fmaf(8.f, v.w, fmaf(4.f, v.z, fmaf(2.f, v.y, v.x)));
    return (unsigned)__float2int_rn(m);
}

// ---------------- K1: table fill (blocks 0..63) + packed pair stream -------
__global__ void __launch_bounds__(TPB) k_main(const float* __restrict__ g,
                                              const float* __restrict__ params) {
    const int tid = threadIdx.x;

    if (blockIdx.x < TFILL) {               // ---- table fill
        float alpha = params[0], beta = params[1], sigma = params[2];
        for (int idx = blockIdx.x * TPB + tid; idx < SPAN * SPAN;
             idx += TFILL * TPB) {
            int b = idx >> SH;              // j-side bin (beta)
            int a = idx & (SPAN - 1);       // i-side bin (alpha)
            float s = alpha * (float)a + beta * (float)b + sigma;
            float p = 1.f / (1.f + expf(s));
            float l0 = logf(1.f - p + EPSV);
            g_Tbase[idx] = l0;
            g_Tdiff[idx] = logf(p + EPSV) - l0;
        }
        return;
    }

    // ---- packed combined-range upper-triangle stream ----------------------
    // Rows rA=pair and rB=NV-1-pair: concatenate their upper-tri float4
    // ranges into ONE contiguous job list of len = lenA+lenB (~2049) slots.
    // Every issued LDG is useful (vs ~50% predicated-off before).
    int pair = blockIdx.x - TFILL;
    int rA = pair, rB = NV - 1 - pair;
    int t0A = rA >> 2, t0B = rB >> 2;
    int lenA = NQ - t0A;
    int len  = lenA + (NQ - t0B);
    const float4* gp = (const float4*)g;
    size_t baseA = (size_t)rA * NQ + t0A;   // float4 index of row A range start
    size_t baseB = (size_t)rB * NQ + t0B;

    unsigned m[9];
#pragma unroll
    for (int k = 0; k < 9; k++) {
        int c = tid + (k << 8);
        unsigned mm = 0;
        if (c < len) {
            bool isA = c < lenA;
            size_t idx = isA ? (baseA + c) : (baseB + (c - lenA));
            mm = nzmask4(__ldcs(gp + idx));
            if (c == 0)    mm &= ~0u << (rA & 3);   // row A leading partial
            if (c == lenA) mm &= ~0u << (rB & 3);   // row B leading partial
        }
        m[k] = mm;
    }

    int degA = 0, degB = 0;
#pragma unroll
    for (int k = 0; k < 9; k++) {
        int pc = __popc(m[k]);
        if (tid + (k << 8) < lenA) degA += pc; else degB += pc;
    }
    int cnt = degA + degB;
    int lane = tid & 31, wid = tid >> 5;

    int dA = degA, dB = degB;
#pragma unroll
    for (int o = 16; o; o >>= 1) {
        dA += __shfl_down_sync(0xffffffffu, dA, o);
        dB += __shfl_down_sync(0xffffffffu, dB, o);
    }
    if (lane == 0) {
        if (dA) atomicAdd(&g_deg[rA], dA);
        if (dB) atomicAdd(&g_deg[rB], dB);
    }

    int inc = cnt;
#pragma unroll
    for (int o = 1; o < 32; o <<= 1) {
        int nn = __shfl_up_sync(0xffffffffu, inc, o);
        if (lane >= o) inc += nn;
    }
    __shared__ int wsum[8], wbase[8], sbase;
    if (lane == 31) wsum[wid] = inc;
    __syncthreads();
    if (tid == 0) {
        int run = 0;
        for (int w = 0; w < 8; w++) { wbase[w] = run; run += wsum[w]; }
        sbase = run ? atomicAdd(&g_ecount, run) : 0;
    }
    __syncthreads();

    int off = sbase + wbase[wid] + inc - cnt;
#pragma unroll
    for (int k = 0; k < 9; k++) {
        unsigned mm = m[k];
        if (!mm) continue;
        int c = tid + (k << 8);
        bool isA = c < lenA;
        int row = isA ? rA : rB;
        int j0 = (int)((isA ? (t0A + c) : (t0B + (c - lenA))) << 2);
        do {
            int b = __ffs(mm) - 1; mm &= mm - 1;
            int j = j0 + b;
            if (off < ECAP) g_edges[off] = ((unsigned)row << 13) | (unsigned)j;
            if (j > row) atomicAdd(&g_deg[j], 1);
            off++;
        } while (mm);
    }
}

// ---------------- K2: base + edges (byte-identical R11 tail) ---------------
__global__ void __launch_bounds__(TPB) k_baseedge(float* __restrict__ out) {
    __shared__ double red[8];
    __shared__ int sdone;
    const int tid = threadIdx.x;
    const int lane = tid & 31, wid = tid >> 5;
    double acc = 0.0;

    if (blockIdx.x < NPART) {
        __shared__ int H[SPAN];
        __shared__ int sbin[PSIZE];
        int p = blockIdx.x;
        if (tid < SPAN) H[tid] = 0;
        __syncthreads();
        for (int i = tid; i < p * PSIZE; i += TPB)
            atomicAdd(&H[min(g_deg[i], SPAN - 1)], 1);
        if (tid < PSIZE) sbin[tid] = min(g_deg[p * PSIZE + tid], SPAN - 1);
        __syncthreads();

        float hb = (float)H[tid];
        float s0 = 0.f, s1 = 0.f;
#pragma unroll
        for (int jj = 0; jj < PSIZE; jj += 2) {
            s0 += g_Tbase[(sbin[jj]     << SH) + tid];
            s1 += g_Tbase[(sbin[jj + 1] << SH) + tid];
        }
        float fa = hb * (s0 + s1);

        for (int idx = tid; idx < NTRI; idx += TPB) {
            int jj = (int)((sqrtf(8.f * (float)idx + 1.f) - 1.f) * 0.5f);
            while ((jj + 1) * (jj + 2) / 2 <= idx) jj++;
            while (jj * (jj + 1) / 2 > idx) jj--;
            int ii = idx - jj * (jj + 1) / 2;
            fa += g_Tbase[(sbin[jj] << SH) + sbin[ii]];
        }
        acc = (double)fa;
    } else {
        int ec = min(g_ecount, ECAP);
        float fa = 0.f;
        for (int e = (blockIdx.x - NPART) * TPB + tid; e < ec;
             e += EBLK * TPB) {
            unsigned pk = g_edges[e];
            int bi = min(g_deg[pk >> 13], SPAN - 1);
            int bj = min(g_deg[pk & 8191u], SPAN - 1);
            fa += g_Tdiff[(bj << SH) + bi];
        }
        acc = (double)fa;
    }

#pragma unroll
    for (int o = 16; o; o >>= 1) acc += __shfl_down_sync(0xffffffffu, acc, o);
    if (lane == 0) red[wid] = acc;
    __syncthreads();
    if (tid == 0) {
        double t = 0.0;
        for (int w = 0; w < 8; w++) t += red[w];
        g_part[blockIdx.x] = t;
        __threadfence();
        sdone = atomicAdd(&g_done, 1);
    }
    __syncthreads();

    if (sdone == GRID_BE - 1) {
        double t = 0.0;
        for (int i = tid; i < GRID_BE; i += TPB) t += g_part[i];
#pragma unroll
        for (int o = 16; o; o >>= 1) t += __shfl_down_sync(0xffffffffu, t, o);
        if (lane == 0) red[wid] = t;
        for (int i = tid; i < NV; i += TPB) g_deg[i] = 0;
        __syncthreads();
        if (tid == 0) {
            double s = 0.0;
            for (int w = 0; w < 8; w++) s += red[w];
            out[0] = -(float)s;
            g_ecount = 0;
            g_done = 0;
        }
    }
}

// ---------------- launch: TWO kernel nodes ----------------
extern "C" void kernel_launch(void* const* d_in, const int* in_sizes, int n_in,
                              void* d_out, int out_size) {
    const float* params = (const float*)d_in[0];  // [3]
    const float* graph  = (const float*)d_in[1];  // [8192*8192]
    k_main<<<NPAIRS + TFILL, TPB>>>(graph, params);
    k_baseedge<<<GRID_BE, TPB>>>((float*)d_out);
}

// round 17
// speedup vs baseline: 1.2829x; 1.2829x over previous
#include <cuda_runtime.h>
#include <cuda_bf16.h>

#define NV 8192
#define EPSV 1e-5f
#define SPAN 256            /* fixed bin range: deg in [0,255] */
#define SH 8                /* table row stride = 256 */
#define ECAP (1 << 22)
#define TPB 256
#define NPAIRS (NV / 2)
#define TFILL 64            /* table-fill blocks appended to k_main */
#define NPART 256           /* base-term partition blocks */
#define PSIZE 32            /* NV / NPART */
#define NTRI (PSIZE * (PSIZE + 1) / 2)
#define EBLK 448
#define GRID_BE (NPART + EBLK)

// ---------- device state (static zero-init; reset by k_baseedge finalizer) --
__device__ int      g_deg[NV];
__device__ unsigned g_edges[ECAP];
__device__ int      g_ecount;
__device__ int      g_done;
__device__ double   g_part[GRID_BE];
__device__ float    g_Tbase[SPAN * SPAN];   // log(1-p+eps),  [bj<<8 | bi]
__device__ float    g_Tdiff[SPAN * SPAN];   // log(p+eps)-log(1-p+eps)

// nonzero mask of a 0/1-valued float4 via exact FFMA chain + F2I (5 ops)
__device__ __forceinline__ unsigned nzmask4(float4 v) {
    float m = fmaf(8.f, v.w, fmaf(4.f, v.z, fmaf(2.f, v.y, v.x)));
    return (unsigned)__float2int_rn(m);
}

// ---------------- K1: table fill + paired-row stream (R15 body, verbatim) --
__global__ void __launch_bounds__(TPB) k_main(const float* __restrict__ g,
                                              const float* __restrict__ params) {
    const int tid = threadIdx.x;

    if (blockIdx.x < TFILL) {               // ---- table fill
        float alpha = params[0], beta = params[1], sigma = params[2];
        for (int idx = blockIdx.x * TPB + tid; idx < SPAN * SPAN;
             idx += TFILL * TPB) {
            int b = idx >> SH;              // j-side bin (beta)
            int a = idx & (SPAN - 1);       // i-side bin (alpha)
            float s = alpha * (float)a + beta * (float)b + sigma;
            float p = 1.f / (1.f + expf(s));
            float l0 = logf(1.f - p + EPSV);
            g_Tbase[idx] = l0;
            g_Tdiff[idx] = logf(p + EPSV) - l0;
        }
        return;
    }

    // ---- paired-row upper-triangle stream, slim ALU (constant offsets =>
    //      ptxas front-batches the 16 LDGs; R16 proved this is load-bearing)
    int pair = blockIdx.x - TFILL;
    int rA = pair, rB = NV - 1 - pair;
    const float4* rpA = (const float4*)(g + (size_t)rA * NV);
    const float4* rpB = (const float4*)(g + (size_t)rB * NV);
    int t0A = rA >> 2, t0B = rB >> 2;
    unsigned umA = 0, umB = 0;
#pragma unroll
    for (int k = 0; k < 8; k++) {
        int ia = t0A + tid + (k << 8);
        if (ia < NV / 4) umA |= nzmask4(__ldcs(&rpA[ia])) << (4 * k);
        int ib = t0B + tid + (k << 8);
        if (ib < NV / 4) umB |= nzmask4(__ldcs(&rpB[ib])) << (4 * k);
    }
    // boundary fix: only idx==t0 (thread 0, chunk 0) can contain j < row.
    if (tid == 0) {
        umA &= ~0u << (rA & 3);
        umB &= ~0u << (rB & 3);
    }

    int cA = __popc(umA), cB = __popc(umB);
    int cnt = cA + cB;
    int lane = tid & 31, wid = tid >> 5;

    int dA = cA, dB = cB;
#pragma unroll
    for (int o = 16; o; o >>= 1) {
        dA += __shfl_down_sync(0xffffffffu, dA, o);
        dB += __shfl_down_sync(0xffffffffu, dB, o);
    }
    if (lane == 0) {
        if (dA) atomicAdd(&g_deg[rA], dA);
        if (dB) atomicAdd(&g_deg[rB], dB);
    }

    int inc = cnt;
#pragma unroll
    for (int o = 1; o < 32; o <<= 1) {
        int nn = __shfl_up_sync(0xffffffffu, inc, o);
        if (lane >= o) inc += nn;
    }
    __shared__ int wsum[8], wbase[8], sbase;
    if (lane == 31) wsum[wid] = inc;
    __syncthreads();
    if (tid == 0) {
        int run = 0;
        for (int w = 0; w < 8; w++) { wbase[w] = run; run += wsum[w]; }
        sbase = run ? atomicAdd(&g_ecount, run) : 0;
    }
    __syncthreads();

    int off = sbase + wbase[wid] + inc - cnt;
    unsigned m2 = umA;
    while (m2) {
        int b = __ffs(m2) - 1; m2 &= m2 - 1;
        int j = ((t0A + tid + ((b >> 2) << 8)) << 2) + (b & 3);
        if (off < ECAP) g_edges[off] = ((unsigned)rA << 13) | (unsigned)j;
        if (j > rA) atomicAdd(&g_deg[j], 1);
        off++;
    }
    m2 = umB;
    while (m2) {
        int b = __ffs(m2) - 1; m2 &= m2 - 1;
        int j = ((t0B + tid + ((b >> 2) << 8)) << 2) + (b & 3);
        if (off < ECAP) g_edges[off] = ((unsigned)rB << 13) | (unsigned)j;
        if (j > rB) atomicAdd(&g_deg[j], 1);
        off++;
    }
}

// ---------------- K2: base + edges with BATCHED loads ----------------------
__global__ void __launch_bounds__(TPB) k_baseedge(float* __restrict__ out) {
    __shared__ double red[8];
    __shared__ int sdone;
    const int tid = threadIdx.x;
    const int lane = tid & 31, wid = tid >> 5;
    double acc = 0.0;

    if (blockIdx.x < NPART) {
        __shared__ int H[SPAN];
        __shared__ int sbin[PSIZE];
        int p = blockIdx.x;
        if (tid < SPAN) H[tid] = 0;
        __syncthreads();

        // histogram of bins for i < p*PSIZE — 4-way batched loads (MLP=4)
        int n = p * PSIZE;
        int i = tid;
        for (; i + 3 * TPB < n; i += 4 * TPB) {
            int d0 = g_deg[i];
            int d1 = g_deg[i + TPB];
            int d2 = g_deg[i + 2 * TPB];
            int d3 = g_deg[i + 3 * TPB];
            atomicAdd(&H[min(d0, SPAN - 1)], 1);
            atomicAdd(&H[min(d1, SPAN - 1)], 1);
            atomicAdd(&H[min(d2, SPAN - 1)], 1);
            atomicAdd(&H[min(d3, SPAN - 1)], 1);
        }
        for (; i < n; i += TPB)
            atomicAdd(&H[min(g_deg[i], SPAN - 1)], 1);
        if (tid < PSIZE) sbin[tid] = min(g_deg[p * PSIZE + tid], SPAN - 1);
        __syncthreads();

        // cross term: thread tid owns column b = tid; H load hoisted
        float hb = (float)H[tid];
        float s0 = 0.f, s1 = 0.f;
#pragma unroll
        for (int jj = 0; jj < PSIZE; jj += 2) {
            s0 += g_Tbase[(sbin[jj]     << SH) + tid];
            s1 += g_Tbase[(sbin[jj + 1] << SH) + tid];
        }
        float fa = hb * (s0 + s1);

        // intra-partition triangle (ii <= jj)
        for (int idx = tid; idx < NTRI; idx += TPB) {
            int jj = (int)((sqrtf(8.f * (float)idx + 1.f) - 1.f) * 0.5f);
            while ((jj + 1) * (jj + 2) / 2 <= idx) jj++;
            while (jj * (jj + 1) / 2 > idx) jj--;
            int ii = idx - jj * (jj + 1) / 2;
            fa += g_Tbase[(sbin[jj] << SH) + sbin[ii]];
        }
        acc = (double)fa;
    } else {
        // edge correction: uint4 = 4 edges/thread; all deg/table loads batched
        int ec = min(g_ecount, ECAP);
        int nq = ec >> 2;
        const uint4* ep = (const uint4*)g_edges;
        float fa = 0.f;
        for (int q = (blockIdx.x - NPART) * TPB + tid; q < nq;
             q += EBLK * TPB) {
            uint4 pk = ep[q];
            int a0 = g_deg[pk.x >> 13], b0 = g_deg[pk.x & 8191u];
            int a1 = g_deg[pk.y >> 13], b1 = g_deg[pk.y & 8191u];
            int a2 = g_deg[pk.z >> 13], b2 = g_deg[pk.z & 8191u];
            int a3 = g_deg[pk.w >> 13], b3 = g_deg[pk.w & 8191u];
            float t0 = g_Tdiff[(min(b0, SPAN - 1) << SH) + min(a0, SPAN - 1)];
            float t1 = g_Tdiff[(min(b1, SPAN - 1) << SH) + min(a1, SPAN - 1)];
            float t2 = g_Tdiff[(min(b2, SPAN - 1) << SH) + min(a2, SPAN - 1)];
            float t3 = g_Tdiff[(min(b3, SPAN - 1) << SH) + min(a3, SPAN - 1)];
            fa += (t0 + t1) + (t2 + t3);
        }
        // remainder edges [nq*4, ec): handled by first threads of block NPART
        if (blockIdx.x == NPART && tid < (ec & 3)) {
            unsigned pk = g_edges[(nq << 2) + tid];
            int bi = min(g_deg[pk >> 13], SPAN - 1);
            int bj = min(g_deg[pk & 8191u], SPAN - 1);
            fa += g_Tdiff[(bj << SH) + bi];
        }
        acc = (double)fa;
    }

#pragma unroll
    for (int o = 16; o; o >>= 1) acc += __shfl_down_sync(0xffffffffu, acc, o);
    if (lane == 0) red[wid] = acc;
    __syncthreads();
    if (tid == 0) {
        double t = 0.0;
        for (int w = 0; w < 8; w++) t += red[w];
        g_part[blockIdx.x] = t;
        __threadfence();
        sdone = atomicAdd(&g_done, 1);
    }
    __syncthreads();

    if (sdone == GRID_BE - 1) {
        double t = 0.0;
        for (int i = tid; i < GRID_BE; i += TPB) t += g_part[i];
#pragma unroll
        for (int o = 16; o; o >>= 1) t += __shfl_down_sync(0xffffffffu, t, o);
        if (lane == 0) red[wid] = t;
        for (int i = tid; i < NV; i += TPB) g_deg[i] = 0;
        __syncthreads();
        if (tid == 0) {
            double s = 0.0;
            for (int w = 0; w < 8; w++) s += red[w];
            out[0] = -(float)s;
            g_ecount = 0;
            g_done = 0;
        }
    }
}

// ---------------- launch: TWO kernel nodes ----------------
extern "C" void kernel_launch(void* const* d_in, const int* in_sizes, int n_in,
                              void* d_out, int out_size) {
    const float* params = (const float*)d_in[0];  // [3]
    const float* graph  = (const float*)d_in[1];  // [8192*8192]
    k_main<<<NPAIRS + TFILL, TPB>>>(graph, params);
    k_baseedge<<<GRID_BE, TPB>>>((float*)d_out);
}